// round 16
// baseline (speedup 1.0000x reference)
#include <cuda_runtime.h>
#include <cuda_bf16.h>
#include <cstdint>

// Problem constants (TRIP log_prob): B=32768, M=8, D=256, R=32
#define MM 8
#define DD 256
#define RR 32
#define NN (RR * RR)          // 1024
#define MT 128                // batch rows per margin block
#define BTOT 32768

#define LOG_2PI_F 1.8378770664093453f

// ---------------- global scratch ----------------
// B fragments pre-permuted for mma.sync m16n8k16 (margins GEMM).
// GEMM n-axis semantic: n = c*32 + j  (j fastest) so n-pairs are j-pairs.
__device__ uint4 g_bf4[MM * 4 * 8 * 16 * 2 * 32];         // 4 MB
// margins in chain-B-fragment order: [b][mode][lane(32)][slot(16)] u32 (2KB per b,mode)
__device__ __nv_bfloat16 g_marg[(size_t)BTOT * MM * NN];  // 512 MB
__device__ float g_s[MM * NN];                            // per-mode core sums (f32)
__device__ float g_lognorm;

// ---------------- helpers ----------------
__device__ __forceinline__ float softplus_f(float x) {
    return (x > 20.0f) ? x : log1pf(expf(x));
}
__device__ __forceinline__ uint32_t bf2_bits(float a, float b) {
    __nv_bfloat162 h = __floats2bfloat162_rn(a, b);  // .x=a (low), .y=b (high)
    return *reinterpret_cast<uint32_t*>(&h);
}
__device__ __forceinline__ uint32_t smem_u32(const void* p) {
    uint32_t a;
    asm("{ .reg .u64 t; cvta.to.shared.u64 t, %1; cvt.u32.u64 %0, t; }" : "=r"(a) : "l"(p));
    return a;
}
__device__ __forceinline__ void ldsm4(uint32_t& r0, uint32_t& r1,
                                      uint32_t& r2, uint32_t& r3, uint32_t addr) {
    asm volatile("ldmatrix.sync.aligned.m8n8.x4.shared.b16 {%0,%1,%2,%3}, [%4];"
                 : "=r"(r0), "=r"(r1), "=r"(r2), "=r"(r3) : "r"(addr));
}
__device__ __forceinline__ void mma_bf16(float* d, const uint32_t* a,
                                         uint32_t b0, uint32_t b1) {
    asm volatile(
        "mma.sync.aligned.m16n8k16.row.col.f32.bf16.bf16.f32 "
        "{%0,%1,%2,%3}, {%4,%5,%6,%7}, {%8,%9}, {%0,%1,%2,%3};"
        : "+f"(d[0]), "+f"(d[1]), "+f"(d[2]), "+f"(d[3])
        : "r"(a[0]), "r"(a[1]), "r"(a[2]), "r"(a[3]), "r"(b0), "r"(b1));
}
__device__ __forceinline__ void stg_cs_128(void* gptr, uint4 v) {
    asm volatile("st.global.cs.v4.u32 [%0], {%1,%2,%3,%4};"
                 :: "l"(gptr), "r"(v.x), "r"(v.y), "r"(v.z), "r"(v.w) : "memory");
}
// swizzled smem address: rows of 512B (256 bf16), 16B chunk XOR (row&7)
__device__ __forceinline__ uint32_t swz(uint32_t base, int row, int chunk) {
    return base + row * 512 + (((chunk) ^ (row & 7)) << 4);
}
// bf16 identity-pair: pack(delta(r==k), delta(r==k+1))
__device__ __forceinline__ uint32_t id_pair(int r, int k) {
    uint32_t v = 0;
    if (r == k)     v |= 0x3F80u;
    if (r == k + 1) v |= 0x3F800000u;
    return v;
}

// ---------------- kernel: prep  softplus(cores) -> B fragments ----------------
// n-axis semantic: j = n&31, c = n>>5  (j fastest)
__global__ void k_prep(const float* __restrict__ cores) {
    int u = blockIdx.x * blockDim.x + threadIdx.x;  // 262144
    int lane = u & 31;
    int half = (u >> 5) & 1;
    int ks = (u >> 6) & 15;
    int g = (u >> 10) & 7;
    int ni = (u >> 13) & 3;
    int mode = u >> 15;
    int ncol = lane >> 2, tig = lane & 3;

    uint4 out;
    uint32_t comp[4];
    #pragma unroll
    for (int c32 = 0; c32 < 4; ++c32) {
        int ntile = half * 2 + (c32 >> 1);
        int isb1 = c32 & 1;
        int n = g * 128 + ni * 32 + ntile * 8 + ncol;
        int d = ks * 16 + isb1 * 8 + tig * 2;
        int jj = n & 31;          // j fastest
        int cc = n >> 5;
        size_t base = (size_t)mode * (DD * NN) + (size_t)d * NN + jj * 32 + cc;
        float x0 = __ldg(&cores[base]);
        float x1 = __ldg(&cores[base + NN]);   // d+1
        comp[c32] = bf2_bits(softplus_f(x0), softplus_f(x1));
    }
    out.x = comp[0]; out.y = comp[1]; out.z = comp[2]; out.w = comp[3];
    g_bf4[u] = out;
}

// ---------------- kernel: per-mode core sums (f32, straight from cores) ----------------
__global__ void k_modesum(const float* __restrict__ cores) {  // grid = MM, 1024 thr
    int mode = blockIdx.x;
    int t = threadIdx.x;
    float a = 0.0f;
    const float* base = cores + (size_t)mode * (DD * NN) + t;
    #pragma unroll 4
    for (int d = 0; d < DD; ++d) a += softplus_f(base[(size_t)d * NN]);
    g_s[mode * NN + t] = a;
}

// ---------------- kernel: norm chain + log(trace) ----------------
__global__ void k_normchain() {  // 1 block, 1024 threads
    __shared__ float nrm[NN];
    __shared__ float s[NN];
    __shared__ float tmp[NN];
    int t = threadIdx.x;
    int r = t >> 5, c = t & 31;
    nrm[t] = g_s[t];
    __syncthreads();
    for (int i = 1; i < MM; ++i) {
        s[t] = g_s[i * NN + t];
        __syncthreads();
        float a = 0.0f;
        #pragma unroll
        for (int j = 0; j < RR; ++j) a += nrm[r * RR + j] * s[j * RR + c];
        tmp[t] = a;
        __syncthreads();
        nrm[t] = tmp[t];
        __syncthreads();
    }
    if (t == 0) {
        float tr = 0.0f;
        #pragma unroll
        for (int k = 0; k < RR; ++k) tr += nrm[k * (RR + 1)];
        g_lognorm = logf(tr);
    }
}

// ---------------- kernel: margins (HMMA m128xn32 warp tiles; 8 warps) ----------------
// Mainloop identical to R14. Store: D-fragment pairs ARE chain B-fragment regs
// (n = c*32+j makes n-pairs j-pairs). Layout per (b,mode): byte = l*64 + slot*4,
// slot = nt_chain*4 + ks*2 + r, where l = nj*4 + (lane&3), nt_chain = cg.
#define M_SMEM 65536

__global__ void __launch_bounds__(256, 1)
k_margins(const float* __restrict__ value,
          const float* __restrict__ location,
          const float* __restrict__ log_scale) {
    extern __shared__ unsigned char sm[];
    __shared__ float sloc[DD], sinv[DD], scb[DD];

    const uint32_t aA = smem_u32(sm);
    const int tid = threadIdx.x;
    const int wid = tid >> 5;      // 0..7 = nj
    const int lane = tid & 31;
    const int mode = blockIdx.x >> 8;
    const int bblk = (blockIdx.x & 255) * MT;

    {
        float lsi = __ldg(&log_scale[tid * MM + mode]);
        sloc[tid] = __ldg(&location[tid * MM + mode]);
        sinv[tid] = __expf(-lsi);
        scb[tid] = -0.5f * LOG_2PI_F - lsi;
    }
    __syncthreads();

    // ---- E tile: Gaussian weights bf16 into swizzled A smem (vector STS.128) ----
    {
        const int b = tid >> 1;
        const int half = tid & 1;
        const float v = __ldg(&value[(size_t)(bblk + b) * MM + mode]);
        #pragma unroll
        for (int c = 0; c < 16; ++c) {
            const int chunk = half * 16 + c;
            uint32_t pr[4];
            #pragma unroll
            for (int e = 0; e < 4; ++e) {
                const int d = chunk * 8 + e * 2;
                float z0 = (v - sloc[d]) * sinv[d];
                float p0 = __expf(fmaf(-0.5f * z0, z0, scb[d]));
                float z1 = (v - sloc[d + 1]) * sinv[d + 1];
                float p1 = __expf(fmaf(-0.5f * z1, z1, scb[d + 1]));
                pr[e] = bf2_bits(p0, p1);
            }
            asm volatile("st.shared.v4.u32 [%0], {%1,%2,%3,%4};"
                         :: "r"(swz(aA, b, chunk)),
                            "r"(pr[0]), "r"(pr[1]), "r"(pr[2]), "r"(pr[3]));
        }
    }
    __syncthreads();

    const int nj = wid;
    const int njh = nj >> 2;
    const int a_row = (lane & 7) + ((lane >> 3) & 1) * 8;
    const int a_cad = lane >> 4;

    const uint4* __restrict__ bbase =
        g_bf4 + (size_t)((mode * 4 + (nj & 3)) * 8192) + lane;

    #define BOFF(t) ((size_t)(((((t) >> 4) * 2 + njh) * 16 + ((t) & 15)) * 64))

    uint4 P0 = __ldg(bbase + BOFF(0)), P1 = __ldg(bbase + BOFF(0) + 32);
    uint4 Q0 = __ldg(bbase + BOFF(1)), Q1 = __ldg(bbase + BOFF(1) + 32);

    // per-warp store offset within the 2KB (b,mode) fragment blob
    const uint32_t woff = (uint32_t)((nj * 4 + (lane & 3)) * 64);

    for (int cg = 0; cg < 4; ++cg) {
        float acc[8][4][4];
        #pragma unroll
        for (int mt = 0; mt < 8; ++mt)
            #pragma unroll
            for (int nt = 0; nt < 4; ++nt)
                #pragma unroll
                for (int e = 0; e < 4; ++e) acc[mt][nt][e] = 0.0f;

        #pragma unroll
        for (int ks = 0; ks < 16; ++ks) {
            int t = cg * 16 + ks + 2;
            t = (t > 63) ? 63 : t;
            uint4 R0 = __ldg(bbase + BOFF(t));
            uint4 R1 = __ldg(bbase + BOFF(t) + 32);

            #pragma unroll
            for (int mt = 0; mt < 8; ++mt) {
                uint32_t a[4];
                ldsm4(a[0], a[1], a[2], a[3],
                      swz(aA, a_row + mt * 16, 2 * ks + a_cad));
                mma_bf16(acc[mt][0], a, P0.x, P0.y);
                mma_bf16(acc[mt][1], a, P0.z, P0.w);
                mma_bf16(acc[mt][2], a, P1.x, P1.y);
                mma_bf16(acc[mt][3], a, P1.z, P1.w);
            }
            P0 = Q0; P1 = Q1; Q0 = R0; Q1 = R1;
        }

        // ---- store: each lane's 4 nt-pairs form one chain B uint4 (no shuffles) ----
        #pragma unroll
        for (int mt = 0; mt < 8; ++mt) {
            uint4 lo, hi;
            lo.x = bf2_bits(acc[mt][0][0], acc[mt][0][1]);
            lo.y = bf2_bits(acc[mt][1][0], acc[mt][1][1]);
            lo.z = bf2_bits(acc[mt][2][0], acc[mt][2][1]);
            lo.w = bf2_bits(acc[mt][3][0], acc[mt][3][1]);
            hi.x = bf2_bits(acc[mt][0][2], acc[mt][0][3]);
            hi.y = bf2_bits(acc[mt][1][2], acc[mt][1][3]);
            hi.z = bf2_bits(acc[mt][2][2], acc[mt][2][3]);
            hi.w = bf2_bits(acc[mt][3][2], acc[mt][3][3]);
            const int b_lo = bblk + mt * 16 + (lane >> 2);
            char* base = (char*)g_marg + ((size_t)b_lo * MM + mode) * 2048 +
                         woff + cg * 16;
            stg_cs_128(base, lo);
            stg_cs_128(base + (size_t)8 * MM * 2048, hi);   // batch b_lo + 8
        }
    }
    #undef BOFF
}

// ---------------- kernel: chain — fully register-resident HMMA ----------------
// One warp = one batch; 8 warps/block; grid = B/8 = 4096. No smem.
// Per mode: 4 coalesced LDG.128 (prefetched 2 modes deep), 16 CVT, 16 HMMA.
// State init = identity A (I @ M0 is exact).
__global__ void __launch_bounds__(256)
k_chain(float* __restrict__ out) {
    const int wid = threadIdx.x >> 5;
    const int lane = threadIdx.x & 31;
    const int b = blockIdx.x * 8 + wid;

    const char* src = (const char*)g_marg + (size_t)b * (MM * 2048) + lane * 64;

    uint4 C0[4], C1[4];
    #pragma unroll
    for (int o = 0; o < 4; ++o) C0[o] = __ldg((const uint4*)(src + o * 16));
    #pragma unroll
    for (int o = 0; o < 4; ++o) C1[o] = __ldg((const uint4*)(src + 2048 + o * 16));

    // identity A-fragments
    uint32_t A[2][2][4];
    {
        const int r1 = lane >> 2;
        const int k0 = 2 * (lane & 3);
        #pragma unroll
        for (int mt = 0; mt < 2; ++mt)
            #pragma unroll
            for (int ks = 0; ks < 2; ++ks) {
                int r = 16 * mt + r1, k = 16 * ks + k0;
                A[mt][ks][0] = id_pair(r, k);
                A[mt][ks][1] = id_pair(r + 8, k);
                A[mt][ks][2] = id_pair(r, k + 8);
                A[mt][ks][3] = id_pair(r + 8, k + 8);
            }
    }

    float D[2][4][4];

    #pragma unroll
    for (int m = 0; m < MM; ++m) {
        uint4 Cn[4];
        if (m + 2 < MM) {
            #pragma unroll
            for (int o = 0; o < 4; ++o)
                Cn[o] = __ldg((const uint4*)(src + (size_t)(m + 2) * 2048 + o * 16));
        }

        #pragma unroll
        for (int mt = 0; mt < 2; ++mt)
            #pragma unroll
            for (int nt = 0; nt < 4; ++nt)
                #pragma unroll
                for (int e = 0; e < 4; ++e) D[mt][nt][e] = 0.0f;

        // B[ks=0][nt][0,1] = C0[nt].x,.y ; B[ks=1][nt][0,1] = C0[nt].z,.w
        #pragma unroll
        for (int mt = 0; mt < 2; ++mt)
            #pragma unroll
            for (int nt = 0; nt < 4; ++nt) {
                mma_bf16(D[mt][nt], A[mt][0], C0[nt].x, C0[nt].y);
                mma_bf16(D[mt][nt], A[mt][1], C0[nt].z, C0[nt].w);
            }

        if (m < MM - 1) {
            #pragma unroll
            for (int mt = 0; mt < 2; ++mt)
                #pragma unroll
                for (int ks = 0; ks < 2; ++ks) {
                    A[mt][ks][0] = bf2_bits(D[mt][2 * ks][0], D[mt][2 * ks][1]);
                    A[mt][ks][1] = bf2_bits(D[mt][2 * ks][2], D[mt][2 * ks][3]);
                    A[mt][ks][2] = bf2_bits(D[mt][2 * ks + 1][0], D[mt][2 * ks + 1][1]);
                    A[mt][ks][3] = bf2_bits(D[mt][2 * ks + 1][2], D[mt][2 * ks + 1][3]);
                }
            #pragma unroll
            for (int o = 0; o < 4; ++o) { C0[o] = C1[o]; C1[o] = Cn[o]; }
        }
    }

    // epilogue: trace of state from D fragments, warp reduce, log
    {
        float tr = 0.0f;
        const int r0 = lane >> 2, c0 = 2 * (lane & 3);
        #pragma unroll
        for (int mt = 0; mt < 2; ++mt)
            #pragma unroll
            for (int nt = 0; nt < 4; ++nt) {
                int rA = 16 * mt + r0, rB = rA + 8, c = 8 * nt + c0;
                if (c == rA)     tr += D[mt][nt][0];
                if (c + 1 == rA) tr += D[mt][nt][1];
                if (c == rB)     tr += D[mt][nt][2];
                if (c + 1 == rB) tr += D[mt][nt][3];
            }
        #pragma unroll
        for (int o = 16; o > 0; o >>= 1) tr += __shfl_xor_sync(0xffffffffu, tr, o);
        if (lane == 0)
            out[b] = logf(fmaxf(tr, 1e-12f)) - g_lognorm;
    }
}

// ---------------- launch ----------------
extern "C" void kernel_launch(void* const* d_in, const int* in_sizes, int n_in,
                              void* d_out, int out_size) {
    const float* value     = (const float*)d_in[0];  // (B, M)
    const float* location  = (const float*)d_in[1];  // (D, M)
    const float* log_scale = (const float*)d_in[2];  // (D, M)
    const float* cores     = (const float*)d_in[3];  // (M, D, R, R)
    float* out = (float*)d_out;

    const int B = in_sizes[0] / MM;   // 32768

    k_prep<<<(MM * 4 * 8 * 16 * 2 * 32) / 256, 256>>>(cores);
    k_modesum<<<MM, 1024>>>(cores);
    k_normchain<<<1, 1024>>>();

    static bool attr_done = false;
    if (!attr_done) {
        cudaFuncSetAttribute(k_margins,
                             cudaFuncAttributeMaxDynamicSharedMemorySize, M_SMEM);
        attr_done = true;
    }

    k_margins<<<(B / MT) * MM, 256, M_SMEM>>>(value, location, log_scale);
    k_chain<<<B / 8, 256>>>(out);
}

// round 17
// speedup vs baseline: 1.1646x; 1.1646x over previous
#include <cuda_runtime.h>
#include <cuda_bf16.h>
#include <cstdint>

// Problem constants (TRIP log_prob): B=32768, M=8, D=256, R=32
#define MM 8
#define DD 256
#define RR 32
#define NN (RR * RR)          // 1024
#define MT 128                // batch rows per margin block
#define BTOT 32768

#define LOG_2PI_F 1.8378770664093453f

// ---------------- global scratch ----------------
// B fragments pre-permuted for mma.sync m16n8k16 (margins GEMM).
// GEMM n-axis semantic: n = c*32 + j  (j fastest) so n-pairs are j-pairs.
__device__ uint4 g_bf4[MM * 4 * 8 * 16 * 2 * 32];         // 4 MB
// margins in chain-B-fragment order, blob per (b,mode) = 2KB:
//   byte = (nj*4 + cg)*64 + q*16   (nj = c>>... warp col-slot, cg = chain nt, q = lane&3)
__device__ __nv_bfloat16 g_marg[(size_t)BTOT * MM * NN];  // 512 MB
__device__ float g_s[MM * NN];                            // per-mode core sums (f32)
__device__ float g_lognorm;

// ---------------- helpers ----------------
__device__ __forceinline__ float softplus_f(float x) {
    return (x > 20.0f) ? x : log1pf(expf(x));
}
__device__ __forceinline__ uint32_t bf2_bits(float a, float b) {
    __nv_bfloat162 h = __floats2bfloat162_rn(a, b);  // .x=a (low), .y=b (high)
    return *reinterpret_cast<uint32_t*>(&h);
}
__device__ __forceinline__ uint32_t smem_u32(const void* p) {
    uint32_t a;
    asm("{ .reg .u64 t; cvta.to.shared.u64 t, %1; cvt.u32.u64 %0, t; }" : "=r"(a) : "l"(p));
    return a;
}
__device__ __forceinline__ void ldsm4(uint32_t& r0, uint32_t& r1,
                                      uint32_t& r2, uint32_t& r3, uint32_t addr) {
    asm volatile("ldmatrix.sync.aligned.m8n8.x4.shared.b16 {%0,%1,%2,%3}, [%4];"
                 : "=r"(r0), "=r"(r1), "=r"(r2), "=r"(r3) : "r"(addr));
}
__device__ __forceinline__ void mma_bf16(float* d, const uint32_t* a,
                                         uint32_t b0, uint32_t b1) {
    asm volatile(
        "mma.sync.aligned.m16n8k16.row.col.f32.bf16.bf16.f32 "
        "{%0,%1,%2,%3}, {%4,%5,%6,%7}, {%8,%9}, {%0,%1,%2,%3};"
        : "+f"(d[0]), "+f"(d[1]), "+f"(d[2]), "+f"(d[3])
        : "r"(a[0]), "r"(a[1]), "r"(a[2]), "r"(a[3]), "r"(b0), "r"(b1));
}
__device__ __forceinline__ void stg_cs_128(void* gptr, uint4 v) {
    asm volatile("st.global.cs.v4.u32 [%0], {%1,%2,%3,%4};"
                 :: "l"(gptr), "r"(v.x), "r"(v.y), "r"(v.z), "r"(v.w) : "memory");
}
// swizzled smem address: rows of 512B (256 bf16), 16B chunk XOR (row&7)
__device__ __forceinline__ uint32_t swz(uint32_t base, int row, int chunk) {
    return base + row * 512 + (((chunk) ^ (row & 7)) << 4);
}
// bf16 identity-pair: pack(delta(r==k), delta(r==k+1))
__device__ __forceinline__ uint32_t id_pair(int r, int k) {
    uint32_t v = 0;
    if (r == k)     v |= 0x3F80u;
    if (r == k + 1) v |= 0x3F800000u;
    return v;
}

// ---------------- kernel: prep  softplus(cores) -> B fragments ----------------
// n-axis semantic: j = n&31, c = n>>5  (j fastest)
__global__ void k_prep(const float* __restrict__ cores) {
    int u = blockIdx.x * blockDim.x + threadIdx.x;  // 262144
    int lane = u & 31;
    int half = (u >> 5) & 1;
    int ks = (u >> 6) & 15;
    int g = (u >> 10) & 7;
    int ni = (u >> 13) & 3;
    int mode = u >> 15;
    int ncol = lane >> 2, tig = lane & 3;

    uint4 out;
    uint32_t comp[4];
    #pragma unroll
    for (int c32 = 0; c32 < 4; ++c32) {
        int ntile = half * 2 + (c32 >> 1);
        int isb1 = c32 & 1;
        int n = g * 128 + ni * 32 + ntile * 8 + ncol;
        int d = ks * 16 + isb1 * 8 + tig * 2;
        int jj = n & 31;          // j fastest
        int cc = n >> 5;
        size_t base = (size_t)mode * (DD * NN) + (size_t)d * NN + jj * 32 + cc;
        float x0 = __ldg(&cores[base]);
        float x1 = __ldg(&cores[base + NN]);   // d+1
        comp[c32] = bf2_bits(softplus_f(x0), softplus_f(x1));
    }
    out.x = comp[0]; out.y = comp[1]; out.z = comp[2]; out.w = comp[3];
    g_bf4[u] = out;
}

// ---------------- kernel: per-mode core sums (f32, straight from cores) ----------------
__global__ void k_modesum(const float* __restrict__ cores) {  // grid = MM, 1024 thr
    int mode = blockIdx.x;
    int t = threadIdx.x;
    float a = 0.0f;
    const float* base = cores + (size_t)mode * (DD * NN) + t;
    #pragma unroll 4
    for (int d = 0; d < DD; ++d) a += softplus_f(base[(size_t)d * NN]);
    g_s[mode * NN + t] = a;
}

// ---------------- kernel: norm chain + log(trace) ----------------
__global__ void k_normchain() {  // 1 block, 1024 threads
    __shared__ float nrm[NN];
    __shared__ float s[NN];
    __shared__ float tmp[NN];
    int t = threadIdx.x;
    int r = t >> 5, c = t & 31;
    nrm[t] = g_s[t];
    __syncthreads();
    for (int i = 1; i < MM; ++i) {
        s[t] = g_s[i * NN + t];
        __syncthreads();
        float a = 0.0f;
        #pragma unroll
        for (int j = 0; j < RR; ++j) a += nrm[r * RR + j] * s[j * RR + c];
        tmp[t] = a;
        __syncthreads();
        nrm[t] = tmp[t];
        __syncthreads();
    }
    if (t == 0) {
        float tr = 0.0f;
        #pragma unroll
        for (int k = 0; k < RR; ++k) tr += nrm[k * (RR + 1)];
        g_lognorm = logf(tr);
    }
}

// ---------------- kernel: margins (HMMA m128xn32 warp tiles; 8 warps) ----------------
// Mainloop identical to R14. Store: lane's 4 nt-pairs ARE one chain B uint4;
// blob layout (b,mode): byte = (nj*4 + cg)*64 + q*16 -> quad writes 64B contiguous.
#define M_SMEM 65536

__global__ void __launch_bounds__(256, 1)
k_margins(const float* __restrict__ value,
          const float* __restrict__ location,
          const float* __restrict__ log_scale) {
    extern __shared__ unsigned char sm[];
    __shared__ float sloc[DD], sinv[DD], scb[DD];

    const uint32_t aA = smem_u32(sm);
    const int tid = threadIdx.x;
    const int wid = tid >> 5;      // 0..7 = nj
    const int lane = tid & 31;
    const int mode = blockIdx.x >> 8;
    const int bblk = (blockIdx.x & 255) * MT;

    {
        float lsi = __ldg(&log_scale[tid * MM + mode]);
        sloc[tid] = __ldg(&location[tid * MM + mode]);
        sinv[tid] = __expf(-lsi);
        scb[tid] = -0.5f * LOG_2PI_F - lsi;
    }
    __syncthreads();

    // ---- E tile: Gaussian weights bf16 into swizzled A smem (vector STS.128) ----
    {
        const int b = tid >> 1;
        const int half = tid & 1;
        const float v = __ldg(&value[(size_t)(bblk + b) * MM + mode]);
        #pragma unroll
        for (int c = 0; c < 16; ++c) {
            const int chunk = half * 16 + c;
            uint32_t pr[4];
            #pragma unroll
            for (int e = 0; e < 4; ++e) {
                const int d = chunk * 8 + e * 2;
                float z0 = (v - sloc[d]) * sinv[d];
                float p0 = __expf(fmaf(-0.5f * z0, z0, scb[d]));
                float z1 = (v - sloc[d + 1]) * sinv[d + 1];
                float p1 = __expf(fmaf(-0.5f * z1, z1, scb[d + 1]));
                pr[e] = bf2_bits(p0, p1);
            }
            asm volatile("st.shared.v4.u32 [%0], {%1,%2,%3,%4};"
                         :: "r"(swz(aA, b, chunk)),
                            "r"(pr[0]), "r"(pr[1]), "r"(pr[2]), "r"(pr[3]));
        }
    }
    __syncthreads();

    const int nj = wid;
    const int njh = nj >> 2;
    const int a_row = (lane & 7) + ((lane >> 3) & 1) * 8;
    const int a_cad = lane >> 4;

    const uint4* __restrict__ bbase =
        g_bf4 + (size_t)((mode * 4 + (nj & 3)) * 8192) + lane;

    #define BOFF(t) ((size_t)(((((t) >> 4) * 2 + njh) * 16 + ((t) & 15)) * 64))

    uint4 P0 = __ldg(bbase + BOFF(0)), P1 = __ldg(bbase + BOFF(0) + 32);
    uint4 Q0 = __ldg(bbase + BOFF(1)), Q1 = __ldg(bbase + BOFF(1) + 32);

    // per-warp/lane store offset within the 2KB (b,mode) blob: nj*256 + q*16 (+cg*64)
    const uint32_t woff = (uint32_t)(nj * 256 + (lane & 3) * 16);

    for (int cg = 0; cg < 4; ++cg) {
        float acc[8][4][4];
        #pragma unroll
        for (int mt = 0; mt < 8; ++mt)
            #pragma unroll
            for (int nt = 0; nt < 4; ++nt)
                #pragma unroll
                for (int e = 0; e < 4; ++e) acc[mt][nt][e] = 0.0f;

        #pragma unroll
        for (int ks = 0; ks < 16; ++ks) {
            int t = cg * 16 + ks + 2;
            t = (t > 63) ? 63 : t;
            uint4 R0 = __ldg(bbase + BOFF(t));
            uint4 R1 = __ldg(bbase + BOFF(t) + 32);

            #pragma unroll
            for (int mt = 0; mt < 8; ++mt) {
                uint32_t a[4];
                ldsm4(a[0], a[1], a[2], a[3],
                      swz(aA, a_row + mt * 16, 2 * ks + a_cad));
                mma_bf16(acc[mt][0], a, P0.x, P0.y);
                mma_bf16(acc[mt][1], a, P0.z, P0.w);
                mma_bf16(acc[mt][2], a, P1.x, P1.y);
                mma_bf16(acc[mt][3], a, P1.z, P1.w);
            }
            P0 = Q0; P1 = Q1; Q0 = R0; Q1 = R1;
        }

        // ---- store: lane's 4 nt-pairs = one chain B uint4; quad = 64B contiguous ----
        #pragma unroll
        for (int mt = 0; mt < 8; ++mt) {
            uint4 lo, hi;
            lo.x = bf2_bits(acc[mt][0][0], acc[mt][0][1]);
            lo.y = bf2_bits(acc[mt][1][0], acc[mt][1][1]);
            lo.z = bf2_bits(acc[mt][2][0], acc[mt][2][1]);
            lo.w = bf2_bits(acc[mt][3][0], acc[mt][3][1]);
            hi.x = bf2_bits(acc[mt][0][2], acc[mt][0][3]);
            hi.y = bf2_bits(acc[mt][1][2], acc[mt][1][3]);
            hi.z = bf2_bits(acc[mt][2][2], acc[mt][2][3]);
            hi.w = bf2_bits(acc[mt][3][2], acc[mt][3][3]);
            const int b_lo = bblk + mt * 16 + (lane >> 2);
            char* base = (char*)g_marg + ((size_t)b_lo * MM + mode) * 2048 +
                         woff + cg * 64;
            stg_cs_128(base, lo);
            stg_cs_128(base + (size_t)8 * MM * 2048, hi);   // batch b_lo + 8
        }
    }
    #undef BOFF
}

// ---------------- kernel: chain — fully register-resident HMMA ----------------
// One warp = one batch; 8 warps/block; grid = B/8 = 4096. No smem.
// Per mode: 4 coalesced LDG.128 (prefetched 2 modes deep), 16 CVT, 16 HMMA.
// Read: lane lc (nj = lc>>2, q = lc&3) reads chain-nt o at nj*256 + o*64 + q*16.
__global__ void __launch_bounds__(256)
k_chain(float* __restrict__ out) {
    const int wid = threadIdx.x >> 5;
    const int lane = threadIdx.x & 31;
    const int b = blockIdx.x * 8 + wid;

    const char* src = (const char*)g_marg + (size_t)b * (MM * 2048) +
                      (lane >> 2) * 256 + (lane & 3) * 16;

    uint4 C0[4], C1[4];
    #pragma unroll
    for (int o = 0; o < 4; ++o) C0[o] = __ldg((const uint4*)(src + o * 64));
    #pragma unroll
    for (int o = 0; o < 4; ++o) C1[o] = __ldg((const uint4*)(src + 2048 + o * 64));

    // identity A-fragments
    uint32_t A[2][2][4];
    {
        const int r1 = lane >> 2;
        const int k0 = 2 * (lane & 3);
        #pragma unroll
        for (int mt = 0; mt < 2; ++mt)
            #pragma unroll
            for (int ks = 0; ks < 2; ++ks) {
                int r = 16 * mt + r1, k = 16 * ks + k0;
                A[mt][ks][0] = id_pair(r, k);
                A[mt][ks][1] = id_pair(r + 8, k);
                A[mt][ks][2] = id_pair(r, k + 8);
                A[mt][ks][3] = id_pair(r + 8, k + 8);
            }
    }

    float D[2][4][4];

    #pragma unroll
    for (int m = 0; m < MM; ++m) {
        uint4 Cn[4];
        if (m + 2 < MM) {
            #pragma unroll
            for (int o = 0; o < 4; ++o)
                Cn[o] = __ldg((const uint4*)(src + (size_t)(m + 2) * 2048 + o * 64));
        }

        #pragma unroll
        for (int mt = 0; mt < 2; ++mt)
            #pragma unroll
            for (int nt = 0; nt < 4; ++nt)
                #pragma unroll
                for (int e = 0; e < 4; ++e) D[mt][nt][e] = 0.0f;

        // B[ks=0][nt][0,1] = C0[nt].x,.y ; B[ks=1][nt][0,1] = C0[nt].z,.w
        #pragma unroll
        for (int mt = 0; mt < 2; ++mt)
            #pragma unroll
            for (int nt = 0; nt < 4; ++nt) {
                mma_bf16(D[mt][nt], A[mt][0], C0[nt].x, C0[nt].y);
                mma_bf16(D[mt][nt], A[mt][1], C0[nt].z, C0[nt].w);
            }

        if (m < MM - 1) {
            #pragma unroll
            for (int mt = 0; mt < 2; ++mt)
                #pragma unroll
                for (int ks = 0; ks < 2; ++ks) {
                    A[mt][ks][0] = bf2_bits(D[mt][2 * ks][0], D[mt][2 * ks][1]);
                    A[mt][ks][1] = bf2_bits(D[mt][2 * ks][2], D[mt][2 * ks][3]);
                    A[mt][ks][2] = bf2_bits(D[mt][2 * ks + 1][0], D[mt][2 * ks + 1][1]);
                    A[mt][ks][3] = bf2_bits(D[mt][2 * ks + 1][2], D[mt][2 * ks + 1][3]);
                }
            #pragma unroll
            for (int o = 0; o < 4; ++o) { C0[o] = C1[o]; C1[o] = Cn[o]; }
        }
    }

    // epilogue: trace of state from D fragments, warp reduce, log
    {
        float tr = 0.0f;
        const int r0 = lane >> 2, c0 = 2 * (lane & 3);
        #pragma unroll
        for (int mt = 0; mt < 2; ++mt)
            #pragma unroll
            for (int nt = 0; nt < 4; ++nt) {
                int rA = 16 * mt + r0, rB = rA + 8, c = 8 * nt + c0;
                if (c == rA)     tr += D[mt][nt][0];
                if (c + 1 == rA) tr += D[mt][nt][1];
                if (c == rB)     tr += D[mt][nt][2];
                if (c + 1 == rB) tr += D[mt][nt][3];
            }
        #pragma unroll
        for (int o = 16; o > 0; o >>= 1) tr += __shfl_xor_sync(0xffffffffu, tr, o);
        if (lane == 0)
            out[b] = logf(fmaxf(tr, 1e-12f)) - g_lognorm;
    }
}

// ---------------- launch ----------------
extern "C" void kernel_launch(void* const* d_in, const int* in_sizes, int n_in,
                              void* d_out, int out_size) {
    const float* value     = (const float*)d_in[0];  // (B, M)
    const float* location  = (const float*)d_in[1];  // (D, M)
    const float* log_scale = (const float*)d_in[2];  // (D, M)
    const float* cores     = (const float*)d_in[3];  // (M, D, R, R)
    float* out = (float*)d_out;

    const int B = in_sizes[0] / MM;   // 32768

    k_prep<<<(MM * 4 * 8 * 16 * 2 * 32) / 256, 256>>>(cores);
    k_modesum<<<MM, 1024>>>(cores);
    k_normchain<<<1, 1024>>>();

    static bool attr_done = false;
    if (!attr_done) {
        cudaFuncSetAttribute(k_margins,
                             cudaFuncAttributeMaxDynamicSharedMemorySize, M_SMEM);
        attr_done = true;
    }

    k_margins<<<(B / MT) * MM, 256, M_SMEM>>>(value, location, log_scale);
    k_chain<<<B / 8, 256>>>(out);
}